// round 14
// baseline (speedup 1.0000x reference)
#include <cuda_runtime.h>
#include <cuda_fp16.h>
#include <math.h>
#include <stdint.h>

#define NN 20000
#define EE 640000
#define DIN 256
#define HID 128
#define HEADSN 4
#define DOUT 128
#define RR 32
#define E2 (EE + NN)
#define W1COLS (HEADSN * HID)   // 512

// ---------------- scratch ----------------
__device__ __align__(256) float  d_counts[NN * RR];
__device__ __align__(256) __half d_countsh[NN * RR];
__device__ __align__(256) int    d_deg[NN];
__device__ __align__(256) int    d_offsets[NN + 1];
__device__ __align__(256) int    d_cursor[NN];
__device__ __align__(256) int2   d_csr[E2];                    // (src, dst)
__device__ __align__(256) __half d_RW1h[RR * W1COLS];
__device__ __align__(256) __half d_xh[(size_t)NN * DIN];
__device__ __align__(256) __half d_W1h[DIN * W1COLS];
__device__ __align__(256) __half d_W2h[W1COLS * DOUT];
__device__ __align__(256) __half d_h1h[(size_t)NN * W1COLS];
__device__ __align__(256) float  d_as1[NN * HEADSN];
__device__ __align__(256) float  d_ad1[NN * HEADSN];
__device__ __align__(256) __half d_agg1h[(size_t)NN * W1COLS];
__device__ __align__(256) __half d_h2h[(size_t)NN * DOUT];
__device__ __align__(256) float  d_as2[NN];
__device__ __align__(256) float  d_ad2[NN];

// ---------------- async copy / ldmatrix helpers ----------------
__device__ __forceinline__ void cp_async16(uint32_t dst, const void* src, int szbytes) {
    asm volatile("cp.async.cg.shared.global [%0], [%1], 16, %2;"
                 :: "r"(dst), "l"(src), "r"(szbytes));
}
__device__ __forceinline__ void cp_commit() { asm volatile("cp.async.commit_group;"); }
template <int NW> __device__ __forceinline__ void cp_wait() {
    asm volatile("cp.async.wait_group %0;" :: "n"(NW));
}
__device__ __forceinline__ void ldsm_x4(uint32_t* r, uint32_t addr) {
    asm volatile("ldmatrix.sync.aligned.m8n8.x4.shared.b16 {%0,%1,%2,%3}, [%4];"
                 : "=r"(r[0]), "=r"(r[1]), "=r"(r[2]), "=r"(r[3]) : "r"(addr));
}
__device__ __forceinline__ void ldsm_x4_t(uint32_t* r, uint32_t addr) {
    asm volatile("ldmatrix.sync.aligned.m8n8.x4.trans.shared.b16 {%0,%1,%2,%3}, [%4];"
                 : "=r"(r[0]), "=r"(r[1]), "=r"(r[2]), "=r"(r[3]) : "r"(addr));
}

// ---------------- init ----------------
__global__ void k_init() {
    int i = blockIdx.x * blockDim.x + threadIdx.x;
    if (i < NN * RR) d_counts[i] = 0.f;
    if (i < NN) { d_deg[i] = 1; d_cursor[i] = 0; }
}

// ---------------- histogram ----------------
__global__ void k_hist(const int* __restrict__ ei, const int* __restrict__ et) {
    int e = blockIdx.x * blockDim.x + threadIdx.x;
    if (e < EE) {
        int s = ei[e];
        int d = ei[EE + e];
        int r = et[e];
        atomicAdd(&d_counts[s * RR + r], 1.0f);
        atomicAdd(&d_deg[d], 1);
    }
}

// ---------------- prep: RW1 gemm + fp16 conversions ----------------
#define PREP_RW1   32
#define PREP_X     1250
#define PREP_CNT   157
#define PREP_W1    32
#define PREP_W2    16
__global__ __launch_bounds__(512) void k_prep(const float* __restrict__ x,
                                              const float* __restrict__ rel,
                                              const float* __restrict__ W1,
                                              const float* __restrict__ W2) {
    int b = blockIdx.x, t = threadIdx.x;
    if (b < PREP_RW1) {
        int r = b, j = t;
        float acc = 0.f;
        const float* rr = rel + r * DIN;
        for (int k = 0; k < DIN; k++)
            acc = fmaf(rr[k], W1[(size_t)k * W1COLS + j], acc);
        d_RW1h[r * W1COLS + j] = __float2half(acc);
    } else if (b < PREP_RW1 + PREP_X) {
        size_t i = (size_t)(b - PREP_RW1) * 4096 + (size_t)t * 8;
#pragma unroll
        for (int q = 0; q < 8; q++) d_xh[i + q] = __float2half(x[i + q]);
    } else if (b < PREP_RW1 + PREP_X + PREP_CNT) {
        size_t i = (size_t)(b - PREP_RW1 - PREP_X) * 4096 + (size_t)t * 8;
#pragma unroll
        for (int q = 0; q < 8; q++)
            if (i + q < (size_t)NN * RR) d_countsh[i + q] = __float2half(d_counts[i + q]);
    } else if (b < PREP_RW1 + PREP_X + PREP_CNT + PREP_W1) {
        size_t i = (size_t)(b - PREP_RW1 - PREP_X - PREP_CNT) * 4096 + (size_t)t * 8;
#pragma unroll
        for (int q = 0; q < 8; q++) d_W1h[i + q] = __float2half(W1[i + q]);
    } else {
        size_t i = (size_t)(b - PREP_RW1 - PREP_X - PREP_CNT - PREP_W1) * 4096 + (size_t)t * 8;
#pragma unroll
        for (int q = 0; q < 8; q++) d_W2h[i + q] = __float2half(W2[i + q]);
    }
}

// ---------------- exclusive scan ----------------
__global__ __launch_bounds__(1024) void k_scan() {
    const int PER = 20;
    int t = threadIdx.x;
    int lane = t & 31, w = t >> 5;
    int base = t * PER;

    int loc[PER];
    int sum = 0;
#pragma unroll
    for (int i = 0; i < PER; i++) {
        int idx = base + i;
        int v = (idx < NN) ? d_deg[idx] : 0;
        loc[i] = sum;
        sum += v;
    }
    int incl = sum;
#pragma unroll
    for (int off = 1; off < 32; off <<= 1) {
        int u = __shfl_up_sync(0xffffffffu, incl, off);
        if (lane >= off) incl += u;
    }
    __shared__ int wincl[32];
    if (lane == 31) wincl[w] = incl;
    __syncthreads();
    if (w == 0) {
        int v = wincl[lane];
        int wi = v;
#pragma unroll
        for (int off = 1; off < 32; off <<= 1) {
            int u = __shfl_up_sync(0xffffffffu, wi, off);
            if (lane >= off) wi += u;
        }
        wincl[lane] = wi;
    }
    __syncthreads();
    int warp_excl = (w == 0) ? 0 : wincl[w - 1];
    int thread_excl = warp_excl + (incl - sum);
#pragma unroll
    for (int i = 0; i < PER; i++) {
        int idx = base + i;
        if (idx < NN) d_offsets[idx] = thread_excl + loc[i];
    }
    if (t == 0) d_offsets[NN] = wincl[31];
}

// ---------------- CSR fill (packed int2) ----------------
__global__ void k_fill(const int* __restrict__ ei) {
    int e = blockIdx.x * blockDim.x + threadIdx.x;
    if (e < EE) {
        int s = ei[e];
        int d = ei[EE + e];
        int pos = d_offsets[d] + atomicAdd(&d_cursor[d], 1);
        d_csr[pos] = make_int2(s, d);
    } else if (e < E2) {
        int n = e - EE;
        int pos = d_offsets[n] + atomicAdd(&d_cursor[n], 1);
        d_csr[pos] = make_int2(n, n);
    }
}

// ---------------- fp16 tensor-core GEMM + fused attention epilogue -----------
// CTA 128x128, BK=32, 8 warps (2m x 4n), 3-stage cp.async pipeline,
// mma.m16n8k16.f16.
template <int MODE>
__global__ __launch_bounds__(256, 2) void k_gemm_tc(const float* __restrict__ att_s,
                                                    const float* __restrict__ att_d)
{
    constexpr int M = NN;
    constexpr int N = (MODE == 0) ? W1COLS : DOUT;
    constexpr int NPASS = (MODE == 0) ? 2 : 1;
    constexpr int BM = 128, BK = 32;
    constexpr int AROW = BK + 8;
    constexpr int BROW = 128 + 8;

    __shared__ __half As[3][BM * AROW];
    __shared__ __half Bs[3][BK * BROW];

    int tid = threadIdx.x;
    int lane = tid & 31, wid = tid >> 5;
    int wm = (wid & 1) * 64;
    int wn = (wid >> 1) * 32;
    int g = lane >> 2, tig = lane & 3;

    int rowBase = blockIdx.y * BM;
    int colBase = blockIdx.x * 128;

    uint32_t aSm[3], bSm[3];
#pragma unroll
    for (int s = 0; s < 3; s++) {
        aSm[s] = (uint32_t)__cvta_generic_to_shared(&As[s][0]);
        bSm[s] = (uint32_t)__cvta_generic_to_shared(&Bs[s][0]);
    }

    int fa_row = tid >> 1;
    int fa_seg = (tid & 1) * 16;
    int fb_row = tid >> 3;
    int fb_seg = (tid & 7) * 16;

    float acc[4][4][4];
#pragma unroll
    for (int mi = 0; mi < 4; mi++)
#pragma unroll
        for (int nj = 0; nj < 4; nj++)
#pragma unroll
            for (int q = 0; q < 4; q++) acc[mi][nj][q] = 0.f;

    int lrow = lane & 15;
    int lcol8 = (lane >> 4) * 8;

#pragma unroll
    for (int pass = 0; pass < NPASS; pass++) {
        const __half* Ap;
        const __half* Bp;
        int Kp;
        if (MODE == 0) {
            if (pass == 0) { Ap = d_xh; Bp = d_W1h; Kp = DIN; }
            else           { Ap = d_countsh; Bp = d_RW1h; Kp = RR; }
        } else {
            Ap = d_agg1h; Bp = d_W2h; Kp = W1COLS;
        }

        int gr = rowBase + fa_row;
        int aOK = (gr < M) ? 16 : 0;
        const __half* aSrc0 = Ap + (size_t)((gr < M) ? gr : (M - 1)) * Kp + fa_seg;
        const __half* bSrc0 = Bp + (size_t)fb_row * N + colBase + fb_seg;
        uint32_t aDst = (uint32_t)(fa_row * AROW + fa_seg) * 2;
        uint32_t bDst = (uint32_t)(fb_row * BROW + fb_seg) * 2;

        int nT = Kp / BK;

        // prologue: issue up to 2 tiles
#pragma unroll
        for (int p = 0; p < 2; p++) {
            if (p < nT) {
                int k0 = p * BK;
                cp_async16(aSm[p] + aDst, aSrc0 + k0, aOK);
                cp_async16(aSm[p] + aDst + 16, aSrc0 + k0 + 8, aOK);
                const __half* bs = bSrc0 + (size_t)k0 * N;
                cp_async16(bSm[p] + bDst, bs, 16);
                cp_async16(bSm[p] + bDst + 16, bs + 8, 16);
                cp_commit();
            }
        }

        for (int kt = 0; kt < nT; kt++) {
            if (kt + 1 < nT) cp_wait<1>(); else cp_wait<0>();
            __syncthreads();

            if (kt + 2 < nT) {
                int buf = (kt + 2) % 3;
                int k0 = (kt + 2) * BK;
                cp_async16(aSm[buf] + aDst, aSrc0 + k0, aOK);
                cp_async16(aSm[buf] + aDst + 16, aSrc0 + k0 + 8, aOK);
                const __half* bs = bSrc0 + (size_t)k0 * N;
                cp_async16(bSm[buf] + bDst, bs, 16);
                cp_async16(bSm[buf] + bDst + 16, bs + 8, 16);
                cp_commit();
            }

            int buf = kt % 3;
#pragma unroll
            for (int kk = 0; kk < BK; kk += 16) {
                uint32_t a[4][4];
#pragma unroll
                for (int mi = 0; mi < 4; mi++) {
                    uint32_t addr = aSm[buf] +
                        (uint32_t)(((wm + mi * 16 + lrow) * AROW + kk + lcol8) * 2);
                    ldsm_x4(a[mi], addr);
                }
                uint32_t bt[2][4];
#pragma unroll
                for (int p = 0; p < 2; p++) {
                    uint32_t addr = bSm[buf] +
                        (uint32_t)(((kk + lrow) * BROW + wn + p * 16 + lcol8) * 2);
                    ldsm_x4_t(bt[p], addr);
                }
#pragma unroll
                for (int mi = 0; mi < 4; mi++)
#pragma unroll
                    for (int nj = 0; nj < 4; nj++) {
                        uint32_t b0 = bt[nj >> 1][(nj & 1) * 2];
                        uint32_t b1 = bt[nj >> 1][(nj & 1) * 2 + 1];
                        asm volatile(
                            "mma.sync.aligned.m16n8k16.row.col.f32.f16.f16.f32 "
                            "{%0,%1,%2,%3}, {%4,%5,%6,%7}, {%8,%9}, {%0,%1,%2,%3};"
                            : "+f"(acc[mi][nj][0]), "+f"(acc[mi][nj][1]),
                              "+f"(acc[mi][nj][2]), "+f"(acc[mi][nj][3])
                            : "r"(a[mi][0]), "r"(a[mi][1]), "r"(a[mi][2]), "r"(a[mi][3]),
                              "r"(b0), "r"(b1));
                    }
            }
        }
        __syncthreads();   // pass boundary: all compute done before buffer reuse
    }

    // ---- store fp16 result tile ----
    __half* Ch = (MODE == 0) ? d_h1h : d_h2h;
#pragma unroll
    for (int mi = 0; mi < 4; mi++) {
#pragma unroll
        for (int nj = 0; nj < 4; nj++) {
            int row = rowBase + wm + mi * 16 + g;
            int col = colBase + wn + nj * 8 + tig * 2;
            if (row < M)
                *(__half2*)&Ch[(size_t)row * N + col] =
                    __floats2half2_rn(acc[mi][nj][0], acc[mi][nj][1]);
            if (row + 8 < M)
                *(__half2*)&Ch[(size_t)(row + 8) * N + col] =
                    __floats2half2_rn(acc[mi][nj][2], acc[mi][nj][3]);
        }
    }

    // ---- fused attention dot products over this CTA's 128 columns ----
    float* red = (float*)&As[0][0];      // 1024 floats: [0..511]=ss, [512..1023]=dd
#pragma unroll
    for (int mi = 0; mi < 4; mi++) {
        float ss_lo = 0.f, dd_lo = 0.f, ss_hi = 0.f, dd_hi = 0.f;
#pragma unroll
        for (int nj = 0; nj < 4; nj++) {
            int col = colBase + wn + nj * 8 + tig * 2;
            float2 sa = *(const float2*)&att_s[col];
            float2 da = *(const float2*)&att_d[col];
            ss_lo += acc[mi][nj][0] * sa.x + acc[mi][nj][1] * sa.y;
            dd_lo += acc[mi][nj][0] * da.x + acc[mi][nj][1] * da.y;
            ss_hi += acc[mi][nj][2] * sa.x + acc[mi][nj][3] * sa.y;
            dd_hi += acc[mi][nj][2] * da.x + acc[mi][nj][3] * da.y;
        }
#pragma unroll
        for (int m = 1; m <= 2; m <<= 1) {
            ss_lo += __shfl_xor_sync(0xffffffffu, ss_lo, m);
            dd_lo += __shfl_xor_sync(0xffffffffu, dd_lo, m);
            ss_hi += __shfl_xor_sync(0xffffffffu, ss_hi, m);
            dd_hi += __shfl_xor_sync(0xffffffffu, dd_hi, m);
        }
        if (tig == 0) {
            int cg = wid >> 1;
            int rl = wm + mi * 16 + g;
            red[rl * 4 + cg] = ss_lo;
            red[512 + rl * 4 + cg] = dd_lo;
            red[(rl + 8) * 4 + cg] = ss_hi;
            red[512 + (rl + 8) * 4 + cg] = dd_hi;
        }
    }
    __syncthreads();
    if (tid < 128) {
        float ss = red[tid * 4] + red[tid * 4 + 1] + red[tid * 4 + 2] + red[tid * 4 + 3];
        float dd = red[512 + tid * 4] + red[512 + tid * 4 + 1] +
                   red[512 + tid * 4 + 2] + red[512 + tid * 4 + 3];
        int grow = rowBase + tid;
        if (grow < M) {
            if (MODE == 0) {
                d_as1[grow * HEADSN + blockIdx.x] = ss;
                d_ad1[grow * HEADSN + blockIdx.x] = dd;
            } else {
                d_as2[grow] = ss;
                d_ad2[grow] = dd;
            }
        }
    }
}

// ---------------- aggregation layer 1 (inline weights, fp16 gathers) ---------
__global__ __launch_bounds__(128) void k_agg1(const float* __restrict__ bias) {
    int n = blockIdx.x;
    int t = threadIdx.x;
    int hh = t >> 5;
    int elt = t * 4;
    int beg = d_offsets[n], end = d_offsets[n + 1];

    float ad = d_ad1[n * HEADSN + hh];

    float den[4] = {0.f, 0.f, 0.f, 0.f};
    float ac[4][4];
#pragma unroll
    for (int u = 0; u < 4; u++)
#pragma unroll
        for (int q = 0; q < 4; q++) ac[u][q] = 0.f;

    int e = beg;
    for (; e + 3 < end; e += 4) {
#pragma unroll
        for (int u = 0; u < 4; u++) {
            int s = d_csr[e + u].x;
            float ev = d_as1[s * HEADSN + hh] + ad;
            ev = ev > 0.f ? ev : 0.2f * ev;
            float w = __expf(ev);
            uint2 p = *(const uint2*)&d_h1h[(size_t)s * W1COLS + elt];
            float2 f01 = __half22float2(*(__half2*)&p.x);
            float2 f23 = __half22float2(*(__half2*)&p.y);
            den[u] += w;
            ac[u][0] = fmaf(w, f01.x, ac[u][0]);
            ac[u][1] = fmaf(w, f01.y, ac[u][1]);
            ac[u][2] = fmaf(w, f23.x, ac[u][2]);
            ac[u][3] = fmaf(w, f23.y, ac[u][3]);
        }
    }
    for (; e < end; e++) {
        int s = d_csr[e].x;
        float ev = d_as1[s * HEADSN + hh] + ad;
        ev = ev > 0.f ? ev : 0.2f * ev;
        float w = __expf(ev);
        uint2 p = *(const uint2*)&d_h1h[(size_t)s * W1COLS + elt];
        float2 f01 = __half22float2(*(__half2*)&p.x);
        float2 f23 = __half22float2(*(__half2*)&p.y);
        den[0] += w;
        ac[0][0] = fmaf(w, f01.x, ac[0][0]);
        ac[0][1] = fmaf(w, f01.y, ac[0][1]);
        ac[0][2] = fmaf(w, f23.x, ac[0][2]);
        ac[0][3] = fmaf(w, f23.y, ac[0][3]);
    }

    float denom = (den[0] + den[1]) + (den[2] + den[3]);
    float inv = 1.f / (denom + 1e-16f);
    float o0 = ((ac[0][0] + ac[1][0]) + (ac[2][0] + ac[3][0])) * inv + bias[elt + 0];
    float o1 = ((ac[0][1] + ac[1][1]) + (ac[2][1] + ac[3][1])) * inv + bias[elt + 1];
    float o2 = ((ac[0][2] + ac[1][2]) + (ac[2][2] + ac[3][2])) * inv + bias[elt + 2];
    float o3 = ((ac[0][3] + ac[1][3]) + (ac[2][3] + ac[3][3])) * inv + bias[elt + 3];
    o0 = o0 > 0.f ? o0 : expm1f(o0);
    o1 = o1 > 0.f ? o1 : expm1f(o1);
    o2 = o2 > 0.f ? o2 : expm1f(o2);
    o3 = o3 > 0.f ? o3 : expm1f(o3);
    __half2 p01 = __floats2half2_rn(o0, o1);
    __half2 p23 = __floats2half2_rn(o2, o3);
    uint2 pk;
    pk.x = *(uint32_t*)&p01;
    pk.y = *(uint32_t*)&p23;
    *(uint2*)&d_agg1h[(size_t)n * W1COLS + elt] = pk;
}

// ---------------- aggregation layer 2 (inline weights, unroll x4) ------------
__global__ __launch_bounds__(128) void k_agg2(const float* __restrict__ bias,
                                              float* __restrict__ out) {
    int n = blockIdx.x;
    int t = threadIdx.x;
    int beg = d_offsets[n], end = d_offsets[n + 1];

    float ad = d_ad2[n];

    float den0 = 0.f, den1 = 0.f, den2 = 0.f, den3 = 0.f;
    float ac0 = 0.f, ac1 = 0.f, ac2 = 0.f, ac3 = 0.f;

    int e = beg;
    for (; e + 3 < end; e += 4) {
        int s0 = d_csr[e].x, s1 = d_csr[e + 1].x;
        int s2 = d_csr[e + 2].x, s3 = d_csr[e + 3].x;
        float ev0 = d_as2[s0] + ad, ev1 = d_as2[s1] + ad;
        float ev2 = d_as2[s2] + ad, ev3 = d_as2[s3] + ad;
        ev0 = ev0 > 0.f ? ev0 : 0.2f * ev0;
        ev1 = ev1 > 0.f ? ev1 : 0.2f * ev1;
        ev2 = ev2 > 0.f ? ev2 : 0.2f * ev2;
        ev3 = ev3 > 0.f ? ev3 : 0.2f * ev3;
        float w0 = __expf(ev0), w1 = __expf(ev1), w2 = __expf(ev2), w3 = __expf(ev3);
        float v0 = __half2float(d_h2h[(size_t)s0 * DOUT + t]);
        float v1 = __half2float(d_h2h[(size_t)s1 * DOUT + t]);
        float v2 = __half2float(d_h2h[(size_t)s2 * DOUT + t]);
        float v3 = __half2float(d_h2h[(size_t)s3 * DOUT + t]);
        den0 += w0; den1 += w1; den2 += w2; den3 += w3;
        ac0 = fmaf(w0, v0, ac0); ac1 = fmaf(w1, v1, ac1);
        ac2 = fmaf(w2, v2, ac2); ac3 = fmaf(w3, v3, ac3);
    }
    for (; e < end; e++) {
        int s0 = d_csr[e].x;
        float ev = d_as2[s0] + ad;
        ev = ev > 0.f ? ev : 0.2f * ev;
        float w0 = __expf(ev);
        float v0 = __half2float(d_h2h[(size_t)s0 * DOUT + t]);
        den0 += w0;
        ac0 = fmaf(w0, v0, ac0);
    }

    float denom = (den0 + den1) + (den2 + den3);
    float acc = (ac0 + ac1) + (ac2 + ac3);
    out[(size_t)n * DOUT + t] = acc / (denom + 1e-16f) + bias[t];
}

// ---------------- host side ----------------
extern "C" void kernel_launch(void* const* d_in, const int* in_sizes, int n_in,
                              void* d_out, int out_size) {
    const float* x    = (const float*)d_in[0];
    const int*   ei   = (const int*)d_in[1];
    const int*   et   = (const int*)d_in[2];
    const float* rel  = (const float*)d_in[3];
    const float* W1   = (const float*)d_in[4];
    const float* as1w = (const float*)d_in[5];
    const float* ad1w = (const float*)d_in[6];
    const float* b1   = (const float*)d_in[7];
    const float* W2   = (const float*)d_in[8];
    const float* as2w = (const float*)d_in[9];
    const float* ad2w = (const float*)d_in[10];
    const float* b2   = (const float*)d_in[11];
    float*       out  = (float*)d_out;

    // launch order keeps gemm0 in the ncu capture slot (4th launch)
    k_init<<<(NN * RR + 255) / 256, 256>>>();
    k_hist<<<(EE + 255) / 256, 256>>>(ei, et);
    k_prep<<<PREP_RW1 + PREP_X + PREP_CNT + PREP_W1 + PREP_W2, 512>>>(x, rel, W1, W2);

    {
        dim3 grid(W1COLS / 128, (NN + 127) / 128);
        k_gemm_tc<0><<<grid, 256>>>(as1w, ad1w);     // <- capture slot (fused attn1)
    }

    k_scan<<<1, 1024>>>();
    k_fill<<<(E2 + 255) / 256, 256>>>(ei);

    k_agg1<<<NN, 128>>>(b1);

    {
        dim3 grid(DOUT / 128, (NN + 127) / 128);
        k_gemm_tc<1><<<grid, 256>>>(as2w, ad2w);     // fused attn2
    }
    k_agg2<<<NN, 128>>>(b2, out);
}

// round 15
// speedup vs baseline: 1.4719x; 1.4719x over previous
#include <cuda_runtime.h>
#include <cuda_fp16.h>
#include <math.h>
#include <stdint.h>

#define NN 20000
#define EE 640000
#define DIN 256
#define HID 128
#define HEADSN 4
#define DOUT 128
#define RR 32
#define E2 (EE + NN)
#define W1COLS (HEADSN * HID)   // 512

// ---------------- scratch ----------------
__device__ __align__(256) float  d_counts[NN * RR];
__device__ __align__(256) __half d_countsh[NN * RR];
__device__ __align__(256) int    d_deg[NN];
__device__ __align__(256) int    d_offsets[NN + 1];
__device__ __align__(256) int    d_cursor[NN];
__device__ __align__(256) int2   d_csr[E2];                    // (src, dst)
__device__ __align__(256) __half d_RW1h[RR * W1COLS];
__device__ __align__(256) __half d_xh[(size_t)NN * DIN];
__device__ __align__(256) __half d_W1h[DIN * W1COLS];
__device__ __align__(256) __half d_W2h[W1COLS * DOUT];
__device__ __align__(256) __half d_h1h[(size_t)NN * W1COLS];
__device__ __align__(256) float  d_as1[NN * HEADSN];
__device__ __align__(256) float  d_ad1[NN * HEADSN];
__device__ __align__(256) float  d_w1[(size_t)E2 * HEADSN];
__device__ __align__(256) __half d_agg1h[(size_t)NN * W1COLS];
__device__ __align__(256) __half d_h2h[(size_t)NN * DOUT];
__device__ __align__(256) float  d_as2[NN];
__device__ __align__(256) float  d_ad2[NN];
__device__ __align__(256) float  d_w2[E2];

// ---------------- async copy / ldmatrix helpers ----------------
__device__ __forceinline__ void cp_async16(uint32_t dst, const void* src, int szbytes) {
    asm volatile("cp.async.cg.shared.global [%0], [%1], 16, %2;"
                 :: "r"(dst), "l"(src), "r"(szbytes));
}
__device__ __forceinline__ void cp_commit() { asm volatile("cp.async.commit_group;"); }
template <int NW> __device__ __forceinline__ void cp_wait() {
    asm volatile("cp.async.wait_group %0;" :: "n"(NW));
}
__device__ __forceinline__ void ldsm_x4(uint32_t* r, uint32_t addr) {
    asm volatile("ldmatrix.sync.aligned.m8n8.x4.shared.b16 {%0,%1,%2,%3}, [%4];"
                 : "=r"(r[0]), "=r"(r[1]), "=r"(r[2]), "=r"(r[3]) : "r"(addr));
}
__device__ __forceinline__ void ldsm_x4_t(uint32_t* r, uint32_t addr) {
    asm volatile("ldmatrix.sync.aligned.m8n8.x4.trans.shared.b16 {%0,%1,%2,%3}, [%4];"
                 : "=r"(r[0]), "=r"(r[1]), "=r"(r[2]), "=r"(r[3]) : "r"(addr));
}

// ---------------- init ----------------
__global__ void k_init() {
    int i = blockIdx.x * blockDim.x + threadIdx.x;
    if (i < NN * RR) d_counts[i] = 0.f;
    if (i < NN) { d_deg[i] = 1; d_cursor[i] = 0; }
}

// ---------------- histogram ----------------
__global__ void k_hist(const int* __restrict__ ei, const int* __restrict__ et) {
    int e = blockIdx.x * blockDim.x + threadIdx.x;
    if (e < EE) {
        int s = ei[e];
        int d = ei[EE + e];
        int r = et[e];
        atomicAdd(&d_counts[s * RR + r], 1.0f);
        atomicAdd(&d_deg[d], 1);
    }
}

// ---------------- prep: block0 = exclusive scan; rest = RW1 + fp16 convert ---
#define PREP_SCAN  1
#define PREP_RW1   32
#define PREP_X     1250
#define PREP_CNT   157
#define PREP_W1    32
#define PREP_W2    16
#define PREP_TOT  (PREP_SCAN + PREP_RW1 + PREP_X + PREP_CNT + PREP_W1 + PREP_W2)
__global__ __launch_bounds__(512) void k_prep(const float* __restrict__ x,
                                              const float* __restrict__ rel,
                                              const float* __restrict__ W1,
                                              const float* __restrict__ W2) {
    int b = blockIdx.x, t = threadIdx.x;
    if (b == 0) {
        // exclusive scan of d_deg (512 threads x 40 elems)
        const int PER = 40;                 // 512*40 = 20480 >= NN
        int lane = t & 31, w = t >> 5;
        int base = t * PER;
        int loc[PER];
        int sum = 0;
#pragma unroll
        for (int i = 0; i < PER; i++) {
            int idx = base + i;
            int v = (idx < NN) ? d_deg[idx] : 0;
            loc[i] = sum;
            sum += v;
        }
        int incl = sum;
#pragma unroll
        for (int off = 1; off < 32; off <<= 1) {
            int u = __shfl_up_sync(0xffffffffu, incl, off);
            if (lane >= off) incl += u;
        }
        __shared__ int wincl[16];
        if (lane == 31) wincl[w] = incl;
        __syncthreads();
        if (w == 0 && lane < 16) {
            int v = wincl[lane];
            int wi = v;
#pragma unroll
            for (int off = 1; off < 16; off <<= 1) {
                int u = __shfl_up_sync(0xffffu, wi, off);
                if (lane >= off) wi += u;
            }
            wincl[lane] = wi;
        }
        __syncthreads();
        int warp_excl = (w == 0) ? 0 : wincl[w - 1];
        int thread_excl = warp_excl + (incl - sum);
#pragma unroll
        for (int i = 0; i < PER; i++) {
            int idx = base + i;
            if (idx < NN) d_offsets[idx] = thread_excl + loc[i];
        }
        if (t == 0) d_offsets[NN] = wincl[15];
    } else if (b < PREP_SCAN + PREP_RW1) {
        int r = b - PREP_SCAN, j = t;
        float acc = 0.f;
        const float* rr = rel + r * DIN;
        for (int k = 0; k < DIN; k++)
            acc = fmaf(rr[k], W1[(size_t)k * W1COLS + j], acc);
        d_RW1h[r * W1COLS + j] = __float2half(acc);
    } else if (b < PREP_SCAN + PREP_RW1 + PREP_X) {
        size_t i = (size_t)(b - PREP_SCAN - PREP_RW1) * 4096 + (size_t)t * 8;
#pragma unroll
        for (int q = 0; q < 8; q++) d_xh[i + q] = __float2half(x[i + q]);
    } else if (b < PREP_SCAN + PREP_RW1 + PREP_X + PREP_CNT) {
        size_t i = (size_t)(b - PREP_SCAN - PREP_RW1 - PREP_X) * 4096 + (size_t)t * 8;
#pragma unroll
        for (int q = 0; q < 8; q++)
            if (i + q < (size_t)NN * RR) d_countsh[i + q] = __float2half(d_counts[i + q]);
    } else if (b < PREP_SCAN + PREP_RW1 + PREP_X + PREP_CNT + PREP_W1) {
        size_t i = (size_t)(b - PREP_SCAN - PREP_RW1 - PREP_X - PREP_CNT) * 4096 + (size_t)t * 8;
#pragma unroll
        for (int q = 0; q < 8; q++) d_W1h[i + q] = __float2half(W1[i + q]);
    } else {
        size_t i = (size_t)(b - PREP_SCAN - PREP_RW1 - PREP_X - PREP_CNT - PREP_W1) * 4096
                 + (size_t)t * 8;
#pragma unroll
        for (int q = 0; q < 8; q++) d_W2h[i + q] = __float2half(W2[i + q]);
    }
}

// ---------------- CSR fill + layer-1 softmax weights (fused) -----------------
// Runs AFTER gemm0 so d_as1/d_ad1 are ready; computes w1[pos] inline.
__global__ void k_fill(const int* __restrict__ ei) {
    int e = blockIdx.x * blockDim.x + threadIdx.x;
    int s, d;
    if (e < EE) {
        s = ei[e];
        d = ei[EE + e];
    } else if (e < E2) {
        s = d = e - EE;
    } else return;
    int pos = d_offsets[d] + atomicAdd(&d_cursor[d], 1);
    d_csr[pos] = make_int2(s, d);
    float4 as = *(const float4*)&d_as1[s * HEADSN];
    float4 ad = *(const float4*)&d_ad1[d * HEADSN];
    float ev0 = as.x + ad.x, ev1 = as.y + ad.y;
    float ev2 = as.z + ad.z, ev3 = as.w + ad.w;
    ev0 = ev0 > 0.f ? ev0 : 0.2f * ev0;
    ev1 = ev1 > 0.f ? ev1 : 0.2f * ev1;
    ev2 = ev2 > 0.f ? ev2 : 0.2f * ev2;
    ev3 = ev3 > 0.f ? ev3 : 0.2f * ev3;
    float4 w;
    w.x = __expf(ev0); w.y = __expf(ev1); w.z = __expf(ev2); w.w = __expf(ev3);
    *(float4*)&d_w1[(size_t)pos * 4] = w;
}

// ---------------- fp16 tensor-core GEMM + fused attention epilogue -----------
// CTA 128x128, BK=32, 8 warps (2m x 4n), 2-stage cp.async (R10/R12-proven),
// mma.m16n8k16.f16.
template <int MODE>
__global__ __launch_bounds__(256, 2) void k_gemm_tc(const float* __restrict__ att_s,
                                                    const float* __restrict__ att_d)
{
    constexpr int M = NN;
    constexpr int N = (MODE == 0) ? W1COLS : DOUT;
    constexpr int NPASS = (MODE == 0) ? 2 : 1;
    constexpr int BM = 128, BK = 32;
    constexpr int AROW = BK + 8;
    constexpr int BROW = 128 + 8;

    __shared__ __half As[2][BM * AROW];
    __shared__ __half Bs[2][BK * BROW];

    int tid = threadIdx.x;
    int lane = tid & 31, wid = tid >> 5;
    int wm = (wid & 1) * 64;
    int wn = (wid >> 1) * 32;
    int g = lane >> 2, tig = lane & 3;

    int rowBase = blockIdx.y * BM;
    int colBase = blockIdx.x * 128;

    uint32_t aSm[2], bSm[2];
    aSm[0] = (uint32_t)__cvta_generic_to_shared(&As[0][0]);
    aSm[1] = (uint32_t)__cvta_generic_to_shared(&As[1][0]);
    bSm[0] = (uint32_t)__cvta_generic_to_shared(&Bs[0][0]);
    bSm[1] = (uint32_t)__cvta_generic_to_shared(&Bs[1][0]);

    int fa_row = tid >> 1;
    int fa_seg = (tid & 1) * 16;
    int fb_row = tid >> 3;
    int fb_seg = (tid & 7) * 16;

    float acc[4][4][4];
#pragma unroll
    for (int mi = 0; mi < 4; mi++)
#pragma unroll
        for (int nj = 0; nj < 4; nj++)
#pragma unroll
            for (int q = 0; q < 4; q++) acc[mi][nj][q] = 0.f;

    int lrow = lane & 15;
    int lcol8 = (lane >> 4) * 8;

#pragma unroll
    for (int pass = 0; pass < NPASS; pass++) {
        const __half* Ap;
        const __half* Bp;
        int Kp;
        if (MODE == 0) {
            if (pass == 0) { Ap = d_xh; Bp = d_W1h; Kp = DIN; }
            else           { Ap = d_countsh; Bp = d_RW1h; Kp = RR; }
        } else {
            Ap = d_agg1h; Bp = d_W2h; Kp = W1COLS;
        }

        int gr = rowBase + fa_row;
        int aOK = (gr < M) ? 16 : 0;
        const __half* aSrc0 = Ap + (size_t)((gr < M) ? gr : (M - 1)) * Kp + fa_seg;
        const __half* bSrc0 = Bp + (size_t)fb_row * N + colBase + fb_seg;
        uint32_t aDst = (uint32_t)(fa_row * AROW + fa_seg) * 2;
        uint32_t bDst = (uint32_t)(fb_row * BROW + fb_seg) * 2;

        int nT = Kp / BK;

        cp_async16(aSm[0] + aDst, aSrc0, aOK);
        cp_async16(aSm[0] + aDst + 16, aSrc0 + 8, aOK);
        cp_async16(bSm[0] + bDst, bSrc0, 16);
        cp_async16(bSm[0] + bDst + 16, bSrc0 + 8, 16);
        cp_commit();

        for (int kt = 0; kt < nT; kt++) {
            if (kt + 1 < nT) {
                int buf = (kt + 1) & 1;
                int k0 = (kt + 1) * BK;
                cp_async16(aSm[buf] + aDst, aSrc0 + k0, aOK);
                cp_async16(aSm[buf] + aDst + 16, aSrc0 + k0 + 8, aOK);
                const __half* bs = bSrc0 + (size_t)k0 * N;
                cp_async16(bSm[buf] + bDst, bs, 16);
                cp_async16(bSm[buf] + bDst + 16, bs + 8, 16);
                cp_commit();
                cp_wait<1>();
            } else {
                cp_wait<0>();
            }
            __syncthreads();

            int buf = kt & 1;
#pragma unroll
            for (int kk = 0; kk < BK; kk += 16) {
                uint32_t a[4][4];
#pragma unroll
                for (int mi = 0; mi < 4; mi++) {
                    uint32_t addr = aSm[buf] +
                        (uint32_t)(((wm + mi * 16 + lrow) * AROW + kk + lcol8) * 2);
                    ldsm_x4(a[mi], addr);
                }
                uint32_t bt[2][4];
#pragma unroll
                for (int p = 0; p < 2; p++) {
                    uint32_t addr = bSm[buf] +
                        (uint32_t)(((kk + lrow) * BROW + wn + p * 16 + lcol8) * 2);
                    ldsm_x4_t(bt[p], addr);
                }
#pragma unroll
                for (int mi = 0; mi < 4; mi++)
#pragma unroll
                    for (int nj = 0; nj < 4; nj++) {
                        uint32_t b0 = bt[nj >> 1][(nj & 1) * 2];
                        uint32_t b1 = bt[nj >> 1][(nj & 1) * 2 + 1];
                        asm volatile(
                            "mma.sync.aligned.m16n8k16.row.col.f32.f16.f16.f32 "
                            "{%0,%1,%2,%3}, {%4,%5,%6,%7}, {%8,%9}, {%0,%1,%2,%3};"
                            : "+f"(acc[mi][nj][0]), "+f"(acc[mi][nj][1]),
                              "+f"(acc[mi][nj][2]), "+f"(acc[mi][nj][3])
                            : "r"(a[mi][0]), "r"(a[mi][1]), "r"(a[mi][2]), "r"(a[mi][3]),
                              "r"(b0), "r"(b1));
                    }
            }
            __syncthreads();
        }
    }

    // ---- store fp16 result tile ----
    __half* Ch = (MODE == 0) ? d_h1h : d_h2h;
#pragma unroll
    for (int mi = 0; mi < 4; mi++) {
#pragma unroll
        for (int nj = 0; nj < 4; nj++) {
            int row = rowBase + wm + mi * 16 + g;
            int col = colBase + wn + nj * 8 + tig * 2;
            if (row < M)
                *(__half2*)&Ch[(size_t)row * N + col] =
                    __floats2half2_rn(acc[mi][nj][0], acc[mi][nj][1]);
            if (row + 8 < M)
                *(__half2*)&Ch[(size_t)(row + 8) * N + col] =
                    __floats2half2_rn(acc[mi][nj][2], acc[mi][nj][3]);
        }
    }

    // ---- fused attention dot products over this CTA's 128 columns ----
    float* red = (float*)&As[0][0];      // 1024 floats: [0..511]=ss, [512..1023]=dd
#pragma unroll
    for (int mi = 0; mi < 4; mi++) {
        float ss_lo = 0.f, dd_lo = 0.f, ss_hi = 0.f, dd_hi = 0.f;
#pragma unroll
        for (int nj = 0; nj < 4; nj++) {
            int col = colBase + wn + nj * 8 + tig * 2;
            float2 sa = *(const float2*)&att_s[col];
            float2 da = *(const float2*)&att_d[col];
            ss_lo += acc[mi][nj][0] * sa.x + acc[mi][nj][1] * sa.y;
            dd_lo += acc[mi][nj][0] * da.x + acc[mi][nj][1] * da.y;
            ss_hi += acc[mi][nj][2] * sa.x + acc[mi][nj][3] * sa.y;
            dd_hi += acc[mi][nj][2] * da.x + acc[mi][nj][3] * da.y;
        }
#pragma unroll
        for (int m = 1; m <= 2; m <<= 1) {
            ss_lo += __shfl_xor_sync(0xffffffffu, ss_lo, m);
            dd_lo += __shfl_xor_sync(0xffffffffu, dd_lo, m);
            ss_hi += __shfl_xor_sync(0xffffffffu, ss_hi, m);
            dd_hi += __shfl_xor_sync(0xffffffffu, dd_hi, m);
        }
        if (tig == 0) {
            int cg = wid >> 1;
            int rl = wm + mi * 16 + g;
            red[rl * 4 + cg] = ss_lo;
            red[512 + rl * 4 + cg] = dd_lo;
            red[(rl + 8) * 4 + cg] = ss_hi;
            red[512 + (rl + 8) * 4 + cg] = dd_hi;
        }
    }
    __syncthreads();
    if (tid < 128) {
        float ss = red[tid * 4] + red[tid * 4 + 1] + red[tid * 4 + 2] + red[tid * 4 + 3];
        float dd = red[512 + tid * 4] + red[512 + tid * 4 + 1] +
                   red[512 + tid * 4 + 2] + red[512 + tid * 4 + 3];
        int grow = rowBase + tid;
        if (grow < M) {
            if (MODE == 0) {
                d_as1[grow * HEADSN + blockIdx.x] = ss;
                d_ad1[grow * HEADSN + blockIdx.x] = dd;
            } else {
                d_as2[grow] = ss;
                d_ad2[grow] = dd;
            }
        }
    }
}

// ---------------- layer-2 softmax weights ----------------
__global__ void k_wt2() {
    int e = blockIdx.x * blockDim.x + threadIdx.x;
    if (e >= E2) return;
    int2 sd = d_csr[e];
    float ev = d_as2[sd.x] + d_ad2[sd.y];
    ev = ev > 0.f ? ev : 0.2f * ev;
    d_w2[e] = __expf(ev);
}

// ---------------- aggregation layer 1 (precomputed w, fp16 gathers, x4) ------
__global__ __launch_bounds__(128) void k_agg1(const float* __restrict__ bias) {
    int n = blockIdx.x;
    int t = threadIdx.x;
    int hh = t >> 5;
    int elt = t * 4;
    int beg = d_offsets[n], end = d_offsets[n + 1];

    float den[4] = {0.f, 0.f, 0.f, 0.f};
    float ac[4][4];
#pragma unroll
    for (int u = 0; u < 4; u++)
#pragma unroll
        for (int q = 0; q < 4; q++) ac[u][q] = 0.f;

    int e = beg;
    for (; e + 3 < end; e += 4) {
#pragma unroll
        for (int u = 0; u < 4; u++) {
            int s = d_csr[e + u].x;
            float4 w4 = *(const float4*)&d_w1[(size_t)(e + u) * 4];
            float w = (hh == 0) ? w4.x : (hh == 1) ? w4.y : (hh == 2) ? w4.z : w4.w;
            uint2 p = *(const uint2*)&d_h1h[(size_t)s * W1COLS + elt];
            float2 f01 = __half22float2(*(__half2*)&p.x);
            float2 f23 = __half22float2(*(__half2*)&p.y);
            den[u] += w;
            ac[u][0] = fmaf(w, f01.x, ac[u][0]);
            ac[u][1] = fmaf(w, f01.y, ac[u][1]);
            ac[u][2] = fmaf(w, f23.x, ac[u][2]);
            ac[u][3] = fmaf(w, f23.y, ac[u][3]);
        }
    }
    for (; e < end; e++) {
        int s = d_csr[e].x;
        float4 w4 = *(const float4*)&d_w1[(size_t)e * 4];
        float w = (hh == 0) ? w4.x : (hh == 1) ? w4.y : (hh == 2) ? w4.z : w4.w;
        uint2 p = *(const uint2*)&d_h1h[(size_t)s * W1COLS + elt];
        float2 f01 = __half22float2(*(__half2*)&p.x);
        float2 f23 = __half22float2(*(__half2*)&p.y);
        den[0] += w;
        ac[0][0] = fmaf(w, f01.x, ac[0][0]);
        ac[0][1] = fmaf(w, f01.y, ac[0][1]);
        ac[0][2] = fmaf(w, f23.x, ac[0][2]);
        ac[0][3] = fmaf(w, f23.y, ac[0][3]);
    }

    float denom = (den[0] + den[1]) + (den[2] + den[3]);
    float inv = 1.f / (denom + 1e-16f);
    float o0 = ((ac[0][0] + ac[1][0]) + (ac[2][0] + ac[3][0])) * inv + bias[elt + 0];
    float o1 = ((ac[0][1] + ac[1][1]) + (ac[2][1] + ac[3][1])) * inv + bias[elt + 1];
    float o2 = ((ac[0][2] + ac[1][2]) + (ac[2][2] + ac[3][2])) * inv + bias[elt + 2];
    float o3 = ((ac[0][3] + ac[1][3]) + (ac[2][3] + ac[3][3])) * inv + bias[elt + 3];
    o0 = o0 > 0.f ? o0 : expm1f(o0);
    o1 = o1 > 0.f ? o1 : expm1f(o1);
    o2 = o2 > 0.f ? o2 : expm1f(o2);
    o3 = o3 > 0.f ? o3 : expm1f(o3);
    __half2 p01 = __floats2half2_rn(o0, o1);
    __half2 p23 = __floats2half2_rn(o2, o3);
    uint2 pk;
    pk.x = *(uint32_t*)&p01;
    pk.y = *(uint32_t*)&p23;
    *(uint2*)&d_agg1h[(size_t)n * W1COLS + elt] = pk;
}

// ---------------- aggregation layer 2 (precomputed w, unroll x4) -------------
__global__ __launch_bounds__(128) void k_agg2(const float* __restrict__ bias,
                                              float* __restrict__ out) {
    int n = blockIdx.x;
    int t = threadIdx.x;
    int beg = d_offsets[n], end = d_offsets[n + 1];

    float den0 = 0.f, den1 = 0.f, den2 = 0.f, den3 = 0.f;
    float ac0 = 0.f, ac1 = 0.f, ac2 = 0.f, ac3 = 0.f;

    int e = beg;
    for (; e + 3 < end; e += 4) {
        int s0 = d_csr[e].x, s1 = d_csr[e + 1].x;
        int s2 = d_csr[e + 2].x, s3 = d_csr[e + 3].x;
        float w0 = d_w2[e], w1 = d_w2[e + 1], w2 = d_w2[e + 2], w3 = d_w2[e + 3];
        float v0 = __half2float(d_h2h[(size_t)s0 * DOUT + t]);
        float v1 = __half2float(d_h2h[(size_t)s1 * DOUT + t]);
        float v2 = __half2float(d_h2h[(size_t)s2 * DOUT + t]);
        float v3 = __half2float(d_h2h[(size_t)s3 * DOUT + t]);
        den0 += w0; den1 += w1; den2 += w2; den3 += w3;
        ac0 = fmaf(w0, v0, ac0); ac1 = fmaf(w1, v1, ac1);
        ac2 = fmaf(w2, v2, ac2); ac3 = fmaf(w3, v3, ac3);
    }
    for (; e < end; e++) {
        int s0 = d_csr[e].x;
        float w0 = d_w2[e];
        float v0 = __half2float(d_h2h[(size_t)s0 * DOUT + t]);
        den0 += w0;
        ac0 = fmaf(w0, v0, ac0);
    }

    float denom = (den0 + den1) + (den2 + den3);
    float acc = (ac0 + ac1) + (ac2 + ac3);
    out[(size_t)n * DOUT + t] = acc / (denom + 1e-16f) + bias[t];
}

// ---------------- host side ----------------
extern "C" void kernel_launch(void* const* d_in, const int* in_sizes, int n_in,
                              void* d_out, int out_size) {
    const float* x    = (const float*)d_in[0];
    const int*   ei   = (const int*)d_in[1];
    const int*   et   = (const int*)d_in[2];
    const float* rel  = (const float*)d_in[3];
    const float* W1   = (const float*)d_in[4];
    const float* as1w = (const float*)d_in[5];
    const float* ad1w = (const float*)d_in[6];
    const float* b1   = (const float*)d_in[7];
    const float* W2   = (const float*)d_in[8];
    const float* as2w = (const float*)d_in[9];
    const float* ad2w = (const float*)d_in[10];
    const float* b2   = (const float*)d_in[11];
    float*       out  = (float*)d_out;

    // order: init(1) hist(2) prep+scan(3) gemm0(4 <- capture slot)
    //        fill+wt0(5) agg1(6) gemm1(7) wt2(8) agg2(9)
    k_init<<<(NN * RR + 255) / 256, 256>>>();
    k_hist<<<(EE + 255) / 256, 256>>>(ei, et);
    k_prep<<<PREP_TOT, 512>>>(x, rel, W1, W2);

    {
        dim3 grid(W1COLS / 128, (NN + 127) / 128);
        k_gemm_tc<0><<<grid, 256>>>(as1w, ad1w);     // fused attn1
    }

    k_fill<<<(E2 + 255) / 256, 256>>>(ei);           // fused wt0

    k_agg1<<<NN, 128>>>(b1);

    {
        dim3 grid(DOUT / 128, (NN + 127) / 128);
        k_gemm_tc<1><<<grid, 256>>>(as2w, ad2w);     // fused attn2
    }
    k_wt2<<<(E2 + 255) / 256, 256>>>();
    k_agg2<<<NN, 128>>>(b2, out);
}

// round 16
// speedup vs baseline: 1.5236x; 1.0351x over previous
#include <cuda_runtime.h>
#include <cuda_fp16.h>
#include <math.h>
#include <stdint.h>

#define NN 20000
#define EE 640000
#define DIN 256
#define HID 128
#define HEADSN 4
#define DOUT 128
#define RR 32
#define E2 (EE + NN)
#define W1COLS (HEADSN * HID)   // 512

// ---------------- scratch ----------------
__device__ __align__(256) float  d_counts[NN * RR];
__device__ __align__(256) __half d_countsh[NN * RR];
__device__ __align__(256) int    d_deg[NN];
__device__ __align__(256) int    d_offsets[NN + 1];
__device__ __align__(256) int    d_cursor[NN];
__device__ __align__(256) int2   d_csr[E2];                    // (src, dst)
__device__ __align__(256) __half d_RW1h[RR * W1COLS];
__device__ __align__(256) __half d_xh[(size_t)NN * DIN];
__device__ __align__(256) __half d_W1h[DIN * W1COLS];
__device__ __align__(256) __half d_W2h[W1COLS * DOUT];
__device__ __align__(256) __half d_h1h[(size_t)NN * W1COLS];
__device__ __align__(256) float  d_as1[NN * HEADSN];
__device__ __align__(256) float  d_ad1[NN * HEADSN];
__device__ __align__(256) float  d_w1[(size_t)E2 * HEADSN];
__device__ __align__(256) __half d_agg1h[(size_t)NN * W1COLS];
__device__ __align__(256) __half d_h2h[(size_t)NN * DOUT];
__device__ __align__(256) float  d_as2[NN];
__device__ __align__(256) float  d_ad2[NN];
__device__ __align__(256) float  d_w2[E2];

// ---------------- async copy / ldmatrix helpers ----------------
__device__ __forceinline__ void cp_async16(uint32_t dst, const void* src, int szbytes) {
    asm volatile("cp.async.cg.shared.global [%0], [%1], 16, %2;"
                 :: "r"(dst), "l"(src), "r"(szbytes));
}
__device__ __forceinline__ void cp_commit() { asm volatile("cp.async.commit_group;"); }
template <int NW> __device__ __forceinline__ void cp_wait() {
    asm volatile("cp.async.wait_group %0;" :: "n"(NW));
}
__device__ __forceinline__ void ldsm_x4(uint32_t* r, uint32_t addr) {
    asm volatile("ldmatrix.sync.aligned.m8n8.x4.shared.b16 {%0,%1,%2,%3}, [%4];"
                 : "=r"(r[0]), "=r"(r[1]), "=r"(r[2]), "=r"(r[3]) : "r"(addr));
}
__device__ __forceinline__ void ldsm_x4_t(uint32_t* r, uint32_t addr) {
    asm volatile("ldmatrix.sync.aligned.m8n8.x4.trans.shared.b16 {%0,%1,%2,%3}, [%4];"
                 : "=r"(r[0]), "=r"(r[1]), "=r"(r[2]), "=r"(r[3]) : "r"(addr));
}

// ---------------- init ----------------
__global__ void k_init() {
    int i = blockIdx.x * blockDim.x + threadIdx.x;
    if (i < NN * RR) d_counts[i] = 0.f;
    if (i < NN) { d_deg[i] = 1; d_cursor[i] = 0; }
}

// ---------------- histogram ----------------
__global__ void k_hist(const int* __restrict__ ei, const int* __restrict__ et) {
    int e = blockIdx.x * blockDim.x + threadIdx.x;
    if (e < EE) {
        int s = ei[e];
        int d = ei[EE + e];
        int r = et[e];
        atomicAdd(&d_counts[s * RR + r], 1.0f);
        atomicAdd(&d_deg[d], 1);
    }
}

// ---------------- prep: block0 = exclusive scan; rest = RW1 + fp16 convert ---
#define PREP_SCAN  1
#define PREP_RW1   32
#define PREP_X     1250
#define PREP_CNT   157
#define PREP_W1    32
#define PREP_W2    16
#define PREP_TOT  (PREP_SCAN + PREP_RW1 + PREP_X + PREP_CNT + PREP_W1 + PREP_W2)
__global__ __launch_bounds__(512) void k_prep(const float* __restrict__ x,
                                              const float* __restrict__ rel,
                                              const float* __restrict__ W1,
                                              const float* __restrict__ W2) {
    int b = blockIdx.x, t = threadIdx.x;
    if (b == 0) {
        const int PER = 40;                 // 512*40 = 20480 >= NN
        int lane = t & 31, w = t >> 5;
        int base = t * PER;
        int loc[PER];
        int sum = 0;
#pragma unroll
        for (int i = 0; i < PER; i++) {
            int idx = base + i;
            int v = (idx < NN) ? d_deg[idx] : 0;
            loc[i] = sum;
            sum += v;
        }
        int incl = sum;
#pragma unroll
        for (int off = 1; off < 32; off <<= 1) {
            int u = __shfl_up_sync(0xffffffffu, incl, off);
            if (lane >= off) incl += u;
        }
        __shared__ int wincl[16];
        if (lane == 31) wincl[w] = incl;
        __syncthreads();
        if (w == 0 && lane < 16) {
            int v = wincl[lane];
            int wi = v;
#pragma unroll
            for (int off = 1; off < 16; off <<= 1) {
                int u = __shfl_up_sync(0xffffu, wi, off);
                if (lane >= off) wi += u;
            }
            wincl[lane] = wi;
        }
        __syncthreads();
        int warp_excl = (w == 0) ? 0 : wincl[w - 1];
        int thread_excl = warp_excl + (incl - sum);
#pragma unroll
        for (int i = 0; i < PER; i++) {
            int idx = base + i;
            if (idx < NN) d_offsets[idx] = thread_excl + loc[i];
        }
        if (t == 0) d_offsets[NN] = wincl[15];
    } else if (b < PREP_SCAN + PREP_RW1) {
        int r = b - PREP_SCAN, j = t;
        float acc = 0.f;
        const float* rr = rel + r * DIN;
        for (int k = 0; k < DIN; k++)
            acc = fmaf(rr[k], W1[(size_t)k * W1COLS + j], acc);
        d_RW1h[r * W1COLS + j] = __float2half(acc);
    } else if (b < PREP_SCAN + PREP_RW1 + PREP_X) {
        size_t i = (size_t)(b - PREP_SCAN - PREP_RW1) * 4096 + (size_t)t * 8;
#pragma unroll
        for (int q = 0; q < 8; q++) d_xh[i + q] = __float2half(x[i + q]);
    } else if (b < PREP_SCAN + PREP_RW1 + PREP_X + PREP_CNT) {
        size_t i = (size_t)(b - PREP_SCAN - PREP_RW1 - PREP_X) * 4096 + (size_t)t * 8;
#pragma unroll
        for (int q = 0; q < 8; q++)
            if (i + q < (size_t)NN * RR) d_countsh[i + q] = __float2half(d_counts[i + q]);
    } else if (b < PREP_SCAN + PREP_RW1 + PREP_X + PREP_CNT + PREP_W1) {
        size_t i = (size_t)(b - PREP_SCAN - PREP_RW1 - PREP_X - PREP_CNT) * 4096 + (size_t)t * 8;
#pragma unroll
        for (int q = 0; q < 8; q++) d_W1h[i + q] = __float2half(W1[i + q]);
    } else {
        size_t i = (size_t)(b - PREP_SCAN - PREP_RW1 - PREP_X - PREP_CNT - PREP_W1) * 4096
                 + (size_t)t * 8;
#pragma unroll
        for (int q = 0; q < 8; q++) d_W2h[i + q] = __float2half(W2[i + q]);
    }
}

// ---------------- CSR fill + layer-1 softmax weights (fused) -----------------
__global__ void k_fill(const int* __restrict__ ei) {
    int e = blockIdx.x * blockDim.x + threadIdx.x;
    int s, d;
    if (e < EE) {
        s = ei[e];
        d = ei[EE + e];
    } else if (e < E2) {
        s = d = e - EE;
    } else return;
    int pos = d_offsets[d] + atomicAdd(&d_cursor[d], 1);
    d_csr[pos] = make_int2(s, d);
    float4 as = *(const float4*)&d_as1[s * HEADSN];
    float4 ad = *(const float4*)&d_ad1[d * HEADSN];
    float ev0 = as.x + ad.x, ev1 = as.y + ad.y;
    float ev2 = as.z + ad.z, ev3 = as.w + ad.w;
    ev0 = ev0 > 0.f ? ev0 : 0.2f * ev0;
    ev1 = ev1 > 0.f ? ev1 : 0.2f * ev1;
    ev2 = ev2 > 0.f ? ev2 : 0.2f * ev2;
    ev3 = ev3 > 0.f ? ev3 : 0.2f * ev3;
    float4 w;
    w.x = __expf(ev0); w.y = __expf(ev1); w.z = __expf(ev2); w.w = __expf(ev3);
    *(float4*)&d_w1[(size_t)pos * 4] = w;
}

// ---------------- fp16 tensor-core GEMM + fused attention epilogue -----------
// MODE 0: BM=128, grid 4x157 (628 CTAs). MODE 1: BM=64, grid 1x313 (full chip).
// 8 warps; warp tile (BM/2)x32; 2-stage cp.async; mma.m16n8k16.f16.
template <int MODE>
__global__ __launch_bounds__(256, 2) void k_gemm_tc(const float* __restrict__ att_s,
                                                    const float* __restrict__ att_d)
{
    constexpr int M = NN;
    constexpr int N = (MODE == 0) ? W1COLS : DOUT;
    constexpr int NPASS = (MODE == 0) ? 2 : 1;
    constexpr int BM = (MODE == 0) ? 128 : 64;
    constexpr int MI = BM / 32;            // m16 tiles per warp (4 or 2)
    constexpr int BK = 32;
    constexpr int AROW = BK + 8;
    constexpr int BROW = 128 + 8;

    __shared__ __half As[2][BM * AROW];
    __shared__ __half Bs[2][BK * BROW];

    int tid = threadIdx.x;
    int lane = tid & 31, wid = tid >> 5;
    int wm = (wid & 1) * (BM / 2);
    int wn = (wid >> 1) * 32;
    int g = lane >> 2, tig = lane & 3;

    int rowBase = blockIdx.y * BM;
    int colBase = blockIdx.x * 128;

    uint32_t aSm[2], bSm[2];
    aSm[0] = (uint32_t)__cvta_generic_to_shared(&As[0][0]);
    aSm[1] = (uint32_t)__cvta_generic_to_shared(&As[1][0]);
    bSm[0] = (uint32_t)__cvta_generic_to_shared(&Bs[0][0]);
    bSm[1] = (uint32_t)__cvta_generic_to_shared(&Bs[1][0]);

    // A fill: BM=128 -> 2 x 16B per thread; BM=64 -> 1 x 16B per thread
    int fa_row = (BM == 128) ? (tid >> 1) : (tid >> 2);
    int fa_seg = (BM == 128) ? ((tid & 1) * 16) : ((tid & 3) * 8);
    int fb_row = tid >> 3;
    int fb_seg = (tid & 7) * 16;

    float acc[MI][4][4];
#pragma unroll
    for (int mi = 0; mi < MI; mi++)
#pragma unroll
        for (int nj = 0; nj < 4; nj++)
#pragma unroll
            for (int q = 0; q < 4; q++) acc[mi][nj][q] = 0.f;

    int lrow = lane & 15;
    int lcol8 = (lane >> 4) * 8;

#pragma unroll
    for (int pass = 0; pass < NPASS; pass++) {
        const __half* Ap;
        const __half* Bp;
        int Kp;
        if (MODE == 0) {
            if (pass == 0) { Ap = d_xh; Bp = d_W1h; Kp = DIN; }
            else           { Ap = d_countsh; Bp = d_RW1h; Kp = RR; }
        } else {
            Ap = d_agg1h; Bp = d_W2h; Kp = W1COLS;
        }

        int gr = rowBase + fa_row;
        int aOK = (gr < M) ? 16 : 0;
        const __half* aSrc0 = Ap + (size_t)((gr < M) ? gr : (M - 1)) * Kp + fa_seg;
        const __half* bSrc0 = Bp + (size_t)fb_row * N + colBase + fb_seg;
        uint32_t aDst = (uint32_t)(fa_row * AROW + fa_seg) * 2;
        uint32_t bDst = (uint32_t)(fb_row * BROW + fb_seg) * 2;

        int nT = Kp / BK;

        cp_async16(aSm[0] + aDst, aSrc0, aOK);
        if (BM == 128) cp_async16(aSm[0] + aDst + 16, aSrc0 + 8, aOK);
        cp_async16(bSm[0] + bDst, bSrc0, 16);
        cp_async16(bSm[0] + bDst + 16, bSrc0 + 8, 16);
        cp_commit();

        for (int kt = 0; kt < nT; kt++) {
            if (kt + 1 < nT) {
                int buf = (kt + 1) & 1;
                int k0 = (kt + 1) * BK;
                cp_async16(aSm[buf] + aDst, aSrc0 + k0, aOK);
                if (BM == 128) cp_async16(aSm[buf] + aDst + 16, aSrc0 + k0 + 8, aOK);
                const __half* bs = bSrc0 + (size_t)k0 * N;
                cp_async16(bSm[buf] + bDst, bs, 16);
                cp_async16(bSm[buf] + bDst + 16, bs + 8, 16);
                cp_commit();
                cp_wait<1>();
            } else {
                cp_wait<0>();
            }
            __syncthreads();

            int buf = kt & 1;
#pragma unroll
            for (int kk = 0; kk < BK; kk += 16) {
                uint32_t a[MI][4];
#pragma unroll
                for (int mi = 0; mi < MI; mi++) {
                    uint32_t addr = aSm[buf] +
                        (uint32_t)(((wm + mi * 16 + lrow) * AROW + kk + lcol8) * 2);
                    ldsm_x4(a[mi], addr);
                }
                uint32_t bt[2][4];
#pragma unroll
                for (int p = 0; p < 2; p++) {
                    uint32_t addr = bSm[buf] +
                        (uint32_t)(((kk + lrow) * BROW + wn + p * 16 + lcol8) * 2);
                    ldsm_x4_t(bt[p], addr);
                }
#pragma unroll
                for (int mi = 0; mi < MI; mi++)
#pragma unroll
                    for (int nj = 0; nj < 4; nj++) {
                        uint32_t b0 = bt[nj >> 1][(nj & 1) * 2];
                        uint32_t b1 = bt[nj >> 1][(nj & 1) * 2 + 1];
                        asm volatile(
                            "mma.sync.aligned.m16n8k16.row.col.f32.f16.f16.f32 "
                            "{%0,%1,%2,%3}, {%4,%5,%6,%7}, {%8,%9}, {%0,%1,%2,%3};"
                            : "+f"(acc[mi][nj][0]), "+f"(acc[mi][nj][1]),
                              "+f"(acc[mi][nj][2]), "+f"(acc[mi][nj][3])
                            : "r"(a[mi][0]), "r"(a[mi][1]), "r"(a[mi][2]), "r"(a[mi][3]),
                              "r"(b0), "r"(b1));
                    }
            }
            __syncthreads();
        }
    }

    // ---- store fp16 result tile ----
    __half* Ch = (MODE == 0) ? d_h1h : d_h2h;
#pragma unroll
    for (int mi = 0; mi < MI; mi++) {
#pragma unroll
        for (int nj = 0; nj < 4; nj++) {
            int row = rowBase + wm + mi * 16 + g;
            int col = colBase + wn + nj * 8 + tig * 2;
            if (row < M)
                *(__half2*)&Ch[(size_t)row * N + col] =
                    __floats2half2_rn(acc[mi][nj][0], acc[mi][nj][1]);
            if (row + 8 < M)
                *(__half2*)&Ch[(size_t)(row + 8) * N + col] =
                    __floats2half2_rn(acc[mi][nj][2], acc[mi][nj][3]);
        }
    }

    // ---- fused attention dot products over this CTA's 128 columns ----
    float* red = (float*)&As[0][0];      // [0..BM*4)=ss, [BM*4..2*BM*4)=dd
#pragma unroll
    for (int mi = 0; mi < MI; mi++) {
        float ss_lo = 0.f, dd_lo = 0.f, ss_hi = 0.f, dd_hi = 0.f;
#pragma unroll
        for (int nj = 0; nj < 4; nj++) {
            int col = colBase + wn + nj * 8 + tig * 2;
            float2 sa = *(const float2*)&att_s[col];
            float2 da = *(const float2*)&att_d[col];
            ss_lo += acc[mi][nj][0] * sa.x + acc[mi][nj][1] * sa.y;
            dd_lo += acc[mi][nj][0] * da.x + acc[mi][nj][1] * da.y;
            ss_hi += acc[mi][nj][2] * sa.x + acc[mi][nj][3] * sa.y;
            dd_hi += acc[mi][nj][2] * da.x + acc[mi][nj][3] * da.y;
        }
#pragma unroll
        for (int m = 1; m <= 2; m <<= 1) {
            ss_lo += __shfl_xor_sync(0xffffffffu, ss_lo, m);
            dd_lo += __shfl_xor_sync(0xffffffffu, dd_lo, m);
            ss_hi += __shfl_xor_sync(0xffffffffu, ss_hi, m);
            dd_hi += __shfl_xor_sync(0xffffffffu, dd_hi, m);
        }
        if (tig == 0) {
            int cg = wid >> 1;
            int rl = wm + mi * 16 + g;
            red[rl * 4 + cg] = ss_lo;
            red[BM * 4 + rl * 4 + cg] = dd_lo;
            red[(rl + 8) * 4 + cg] = ss_hi;
            red[BM * 4 + (rl + 8) * 4 + cg] = dd_hi;
        }
    }
    __syncthreads();
    if (tid < BM) {
        float ss = red[tid * 4] + red[tid * 4 + 1] + red[tid * 4 + 2] + red[tid * 4 + 3];
        float dd = red[BM * 4 + tid * 4] + red[BM * 4 + tid * 4 + 1] +
                   red[BM * 4 + tid * 4 + 2] + red[BM * 4 + tid * 4 + 3];
        int grow = rowBase + tid;
        if (grow < M) {
            if (MODE == 0) {
                d_as1[grow * HEADSN + blockIdx.x] = ss;
                d_ad1[grow * HEADSN + blockIdx.x] = dd;
            } else {
                d_as2[grow] = ss;
                d_ad2[grow] = dd;
            }
        }
    }
}

// ---------------- layer-2 softmax weights ----------------
__global__ void k_wt2() {
    int e = blockIdx.x * blockDim.x + threadIdx.x;
    if (e >= E2) return;
    int2 sd = d_csr[e];
    float ev = d_as2[sd.x] + d_ad2[sd.y];
    ev = ev > 0.f ? ev : 0.2f * ev;
    d_w2[e] = __expf(ev);
}

// ---------------- aggregation layer 1 (precomputed w, fp16 gathers, x4) ------
__global__ __launch_bounds__(128) void k_agg1(const float* __restrict__ bias) {
    int n = blockIdx.x;
    int t = threadIdx.x;
    int hh = t >> 5;
    int elt = t * 4;
    int beg = d_offsets[n], end = d_offsets[n + 1];

    float den[4] = {0.f, 0.f, 0.f, 0.f};
    float ac[4][4];
#pragma unroll
    for (int u = 0; u < 4; u++)
#pragma unroll
        for (int q = 0; q < 4; q++) ac[u][q] = 0.f;

    int e = beg;
    for (; e + 3 < end; e += 4) {
#pragma unroll
        for (int u = 0; u < 4; u++) {
            int s = d_csr[e + u].x;
            float4 w4 = *(const float4*)&d_w1[(size_t)(e + u) * 4];
            float w = (hh == 0) ? w4.x : (hh == 1) ? w4.y : (hh == 2) ? w4.z : w4.w;
            uint2 p = *(const uint2*)&d_h1h[(size_t)s * W1COLS + elt];
            float2 f01 = __half22float2(*(__half2*)&p.x);
            float2 f23 = __half22float2(*(__half2*)&p.y);
            den[u] += w;
            ac[u][0] = fmaf(w, f01.x, ac[u][0]);
            ac[u][1] = fmaf(w, f01.y, ac[u][1]);
            ac[u][2] = fmaf(w, f23.x, ac[u][2]);
            ac[u][3] = fmaf(w, f23.y, ac[u][3]);
        }
    }
    for (; e < end; e++) {
        int s = d_csr[e].x;
        float4 w4 = *(const float4*)&d_w1[(size_t)e * 4];
        float w = (hh == 0) ? w4.x : (hh == 1) ? w4.y : (hh == 2) ? w4.z : w4.w;
        uint2 p = *(const uint2*)&d_h1h[(size_t)s * W1COLS + elt];
        float2 f01 = __half22float2(*(__half2*)&p.x);
        float2 f23 = __half22float2(*(__half2*)&p.y);
        den[0] += w;
        ac[0][0] = fmaf(w, f01.x, ac[0][0]);
        ac[0][1] = fmaf(w, f01.y, ac[0][1]);
        ac[0][2] = fmaf(w, f23.x, ac[0][2]);
        ac[0][3] = fmaf(w, f23.y, ac[0][3]);
    }

    float denom = (den[0] + den[1]) + (den[2] + den[3]);
    float inv = 1.f / (denom + 1e-16f);
    float o0 = ((ac[0][0] + ac[1][0]) + (ac[2][0] + ac[3][0])) * inv + bias[elt + 0];
    float o1 = ((ac[0][1] + ac[1][1]) + (ac[2][1] + ac[3][1])) * inv + bias[elt + 1];
    float o2 = ((ac[0][2] + ac[1][2]) + (ac[2][2] + ac[3][2])) * inv + bias[elt + 2];
    float o3 = ((ac[0][3] + ac[1][3]) + (ac[2][3] + ac[3][3])) * inv + bias[elt + 3];
    o0 = o0 > 0.f ? o0 : expm1f(o0);
    o1 = o1 > 0.f ? o1 : expm1f(o1);
    o2 = o2 > 0.f ? o2 : expm1f(o2);
    o3 = o3 > 0.f ? o3 : expm1f(o3);
    __half2 p01 = __floats2half2_rn(o0, o1);
    __half2 p23 = __floats2half2_rn(o2, o3);
    uint2 pk;
    pk.x = *(uint32_t*)&p01;
    pk.y = *(uint32_t*)&p23;
    *(uint2*)&d_agg1h[(size_t)n * W1COLS + elt] = pk;
}

// ---------------- aggregation layer 2 (precomputed w, unroll x4) -------------
__global__ __launch_bounds__(128) void k_agg2(const float* __restrict__ bias,
                                              float* __restrict__ out) {
    int n = blockIdx.x;
    int t = threadIdx.x;
    int beg = d_offsets[n], end = d_offsets[n + 1];

    float den0 = 0.f, den1 = 0.f, den2 = 0.f, den3 = 0.f;
    float ac0 = 0.f, ac1 = 0.f, ac2 = 0.f, ac3 = 0.f;

    int e = beg;
    for (; e + 3 < end; e += 4) {
        int s0 = d_csr[e].x, s1 = d_csr[e + 1].x;
        int s2 = d_csr[e + 2].x, s3 = d_csr[e + 3].x;
        float w0 = d_w2[e], w1 = d_w2[e + 1], w2 = d_w2[e + 2], w3 = d_w2[e + 3];
        float v0 = __half2float(d_h2h[(size_t)s0 * DOUT + t]);
        float v1 = __half2float(d_h2h[(size_t)s1 * DOUT + t]);
        float v2 = __half2float(d_h2h[(size_t)s2 * DOUT + t]);
        float v3 = __half2float(d_h2h[(size_t)s3 * DOUT + t]);
        den0 += w0; den1 += w1; den2 += w2; den3 += w3;
        ac0 = fmaf(w0, v0, ac0); ac1 = fmaf(w1, v1, ac1);
        ac2 = fmaf(w2, v2, ac2); ac3 = fmaf(w3, v3, ac3);
    }
    for (; e < end; e++) {
        int s0 = d_csr[e].x;
        float w0 = d_w2[e];
        float v0 = __half2float(d_h2h[(size_t)s0 * DOUT + t]);
        den0 += w0;
        ac0 = fmaf(w0, v0, ac0);
    }

    float denom = (den0 + den1) + (den2 + den3);
    float acc = (ac0 + ac1) + (ac2 + ac3);
    out[(size_t)n * DOUT + t] = acc / (denom + 1e-16f) + bias[t];
}

// ---------------- host side ----------------
extern "C" void kernel_launch(void* const* d_in, const int* in_sizes, int n_in,
                              void* d_out, int out_size) {
    const float* x    = (const float*)d_in[0];
    const int*   ei   = (const int*)d_in[1];
    const int*   et   = (const int*)d_in[2];
    const float* rel  = (const float*)d_in[3];
    const float* W1   = (const float*)d_in[4];
    const float* as1w = (const float*)d_in[5];
    const float* ad1w = (const float*)d_in[6];
    const float* b1   = (const float*)d_in[7];
    const float* W2   = (const float*)d_in[8];
    const float* as2w = (const float*)d_in[9];
    const float* ad2w = (const float*)d_in[10];
    const float* b2   = (const float*)d_in[11];
    float*       out  = (float*)d_out;

    // order: init(1) hist(2) prep+scan(3) gemm0(4 <- capture slot)
    //        fill+wt0(5) agg1(6) gemm1(7) wt2(8) agg2(9)
    k_init<<<(NN * RR + 255) / 256, 256>>>();
    k_hist<<<(EE + 255) / 256, 256>>>(ei, et);
    k_prep<<<PREP_TOT, 512>>>(x, rel, W1, W2);

    {
        dim3 grid(W1COLS / 128, (NN + 127) / 128);
        k_gemm_tc<0><<<grid, 256>>>(as1w, ad1w);     // fused attn1, BM=128
    }

    k_fill<<<(E2 + 255) / 256, 256>>>(ei);           // fused wt0

    k_agg1<<<NN, 128>>>(b1);

    {
        dim3 grid(DOUT / 128, (NN + 63) / 64);
        k_gemm_tc<1><<<grid, 256>>>(as2w, ad2w);     // fused attn2, BM=64
    }
    k_wt2<<<(E2 + 255) / 256, 256>>>();
    k_agg2<<<NN, 128>>>(b2, out);
}